// round 8
// baseline (speedup 1.0000x reference)
#include <cuda_runtime.h>
#include <math.h>

// ---------------------------------------------------------------------------
// ElectricOverflow. Grid 512x512x8 (8MB, L2-resident), padded both sides.
//
// Validated cost model (R2-R7): scatter cost ~ distinct 32B L2 sectors
// touched per (node, xy-cell) (~1.83M); lane/instruction-count variants are
// neutral (same-sector REDs merge). LTS runs at 60% -> this round doubles
// per-warp outstanding REDs (2 nodes/thread) to raise LTS feed.
//
// Launch order [scatter, reduce, zero]: device globals start zeroed; the
// trailing zero restores the invariant each replay (and keeps the scatter
// at ncu's fixed capture index).
// ---------------------------------------------------------------------------

#define NM_ 250000
#define NT_ 8000
#define NF_ 60000
#define N_  (NM_ + NT_ + NF_)    // 318000
#define H_  (N_ / 2)             // 159000 (nodes per thread = 2)
#define NX_ 512
#define NY_ 512
#define NZ_ 8
#define NBINS_ (NX_ * NY_ * NZ_) // 2097152
#define PADF_ 4424               // covers ix/iy in [-1,512], z window [-2,9]

#define SQRT2H 0.7071067811865476f
#define C1 0.41421356237309515f  // sqrt2 - 1
#define C2 0.5857864376269049f   // 2 - sqrt2

__device__ float g_pad[PADF_ + NBINS_ + PADF_];
#define GRID_B (g_pad + PADF_)

__device__ __forceinline__ void red1(float* p, float v) {
    asm volatile("red.global.add.f32 [%0], %1;" :: "l"(p), "f"(v) : "memory");
}
__device__ __forceinline__ void red2(float* p, float a, float b) {
    asm volatile("red.global.add.v2.f32 [%0], {%1, %2};"
                 :: "l"(p), "f"(a), "f"(b) : "memory");
}

// Process one node given its (preloaded) inputs. isFill is warp-uniform-ish.
__device__ __forceinline__ void scatter_node(bool isFill,
                                             float sx, float sy, float sz,
                                             float px, float py, float pz) {
    if (!isFill) {
        // movable/fixed: clamped size = sqrt2 on every axis
        const float w = sx * sy * sz * 0.35355339059327373f;  // /(2*sqrt2)
        float x0 = px + 0.5f * sx - SQRT2H;
        float y0 = py + 0.5f * sy - SQRT2H;
        float z0 = pz + 0.5f * sz - SQRT2H;

        float fxf = floorf(x0), fyf = floorf(y0), fzf = floorf(z0);
        int ix0 = (int)fxf, iy0 = (int)fyf, iz0 = (int)fzf;  // iz0 in [-1,6]
        float fx = x0 - fxf, fy = y0 - fyf, fz = z0 - fzf;

        float ox[3] = { 1.0f - fx, fminf(fx + C1, 1.0f), fmaxf(fx - C2, 0.0f) };
        float oy[3] = { 1.0f - fy, fminf(fy + C1, 1.0f), fmaxf(fy - C2, 0.0f) };

        float v0 = 1.0f - fz;
        float v1 = fminf(fz + C1, 1.0f);
        float v2 = fmaxf(fz - C2, 0.0f);

        // branch-free 4-wide z window at 8B-aligned base; out-of-row slots
        // land on border bins (dead) or padding (never read)
        bool even = ((iz0 & 1) == 0);
        int zbase = iz0 & ~1;
        float za0 = even ? v0 : 0.0f;
        float za1 = even ? v1 : v0;
        float za2 = even ? v2 : v1;
        float za3 = even ? 0.0f : v2;

        int rowbase = ((ix0 * NY_ + iy0) << 3) + zbase;
#pragma unroll
        for (int a = 0; a < 3; ++a) {
            if (ox[a] == 0.0f) continue;          // only a==2 can be 0
            float wx = w * ox[a];
#pragma unroll
            for (int b = 0; b < 3; ++b) {
                if (oy[b] == 0.0f) continue;
                float wxy = wx * oy[b];
                float* p = GRID_B + rowbase + ((a * NY_ + b) << 3);
                red2(p,     wxy * za0, wxy * za1);
                red2(p + 2, wxy * za2, wxy * za3);
            }
        }
    } else {
        // filler: raw sizes < 1 -> <= 2 bins/axis, weight 1 (8k nodes)
        float fxf = floorf(px), fyf = floorf(py), fzf = floorf(pz);
        int ix0 = (int)fxf, iy0 = (int)fyf, iz0 = (int)fzf;  // iz0 in [0,6]
        float fx = px - fxf, fy = py - fyf, fz = pz - fzf;

        float ox[2] = { fminf(1.0f - fx, sx), fmaxf(fx + sx - 1.0f, 0.0f) };
        float oy[2] = { fminf(1.0f - fy, sy), fmaxf(fy + sy - 1.0f, 0.0f) };
        float v0 = fminf(1.0f - fz, sz);
        float v1 = fmaxf(fz + sz - 1.0f, 0.0f);
        bool e0 = (iz0 >= 1);
        bool e1 = (iz0 <= 5) & (v1 > 0.0f);
        if (!(e0 | e1)) return;
        bool even0 = ((iz0 & 1) == 0);

#pragma unroll
        for (int a = 0; a < 2; ++a) {
            if (ox[a] == 0.0f) continue;
#pragma unroll
            for (int b = 0; b < 2; ++b) {
                if (oy[b] == 0.0f) continue;
                float wxy = ox[a] * oy[b];
                float* p = GRID_B + (((ix0 + a) * NY_ + (iy0 + b)) << 3) + iz0;
                if (e0 && e1 && even0) red2(p, wxy * v0, wxy * v1);
                else {
                    if (e0) red1(p, wxy * v0);
                    if (e1) red1(p + 1, wxy * v1);
                }
            }
        }
    }
}

// ---------------------------------------------------------------------------
// Fused scatter, 2 nodes per thread (doubles outstanding REDs per warp).
// Node n: mf if n < NM+NF (j = n or n+NT), filler otherwise (j = n-NF).
// ---------------------------------------------------------------------------
__global__ void k_scatter(const float* __restrict__ pos,
                          const float* __restrict__ nsx,
                          const float* __restrict__ nsy,
                          const float* __restrict__ nsz,
                          float* __restrict__ out) {
    int t = blockIdx.x * blockDim.x + threadIdx.x;
    if (t >= H_) return;
    if (t == 0) { out[0] = 0.0f; out[1] = 1.0f; }   // border density = 1.0

    // node A = t (always mf), node B = t + H_
    int nB = t + H_;
    bool fillB = (nB >= NM_ + NF_);
    int jA = (t < NM_) ? t : (t + NT_);
    int jB = fillB ? (nB - NF_) : ((nB < NM_) ? nB : (nB + NT_));

    // batch all 12 independent loads up front
    float sxA = nsx[jA], syA = nsy[jA], szA = nsz[jA];
    float pxA = pos[jA], pyA = pos[N_ + jA], pzA = pos[2 * N_ + jA];
    float sxB = nsx[jB], syB = nsy[jB], szB = nsz[jB];
    float pxB = pos[jB], pyB = pos[N_ + jB], pzB = pos[2 * N_ + jB];

    scatter_node(false, sxA, syA, szA, pxA, pyA, pzA);
    scatter_node(fillB, sxB, syB, szB, pxB, pyB, pzB);
}

// ---------------------------------------------------------------------------
// Reduction (load-only): one thread per (x,y) z-row, 2x float4, interior
// z=1..6. Border rows skipped (cost 0; max floor 1.0 seeded in k_scatter).
// ---------------------------------------------------------------------------
__global__ void k_reduce(float* __restrict__ out) {
    int t = blockIdx.x * blockDim.x + threadIdx.x;  // 512*512 threads
    float s = 0.0f, m = 0.0f;
    int ix = t >> 9;
    int iy = t & 511;
    if (ix >= 1 && ix <= NX_ - 2 && iy >= 1 && iy <= NY_ - 2) {
        const float4* g4 = reinterpret_cast<const float4*>(GRID_B) + t * 2;
        float4 a = g4[0];
        float4 b = g4[1];
        s = fmaxf(a.y - 1.0f, 0.0f) + fmaxf(a.z - 1.0f, 0.0f) +
            fmaxf(a.w - 1.0f, 0.0f) + fmaxf(b.x - 1.0f, 0.0f) +
            fmaxf(b.y - 1.0f, 0.0f) + fmaxf(b.z - 1.0f, 0.0f);
        m = fmaxf(fmaxf(fmaxf(a.y, a.z), fmaxf(a.w, b.x)), fmaxf(b.y, b.z));
    }
#pragma unroll
    for (int o = 16; o > 0; o >>= 1) {
        s += __shfl_down_sync(0xffffffffu, s, o);
        m = fmaxf(m, __shfl_down_sync(0xffffffffu, m, o));
    }
    __shared__ float ss[8], sm[8];
    int lane = threadIdx.x & 31;
    int wid = threadIdx.x >> 5;
    if (lane == 0) { ss[wid] = s; sm[wid] = m; }
    __syncthreads();
    if (wid == 0) {
        int nw = blockDim.x >> 5;
        s = (lane < nw) ? ss[lane] : 0.0f;
        m = (lane < nw) ? sm[lane] : 0.0f;
#pragma unroll
        for (int o = 4; o > 0; o >>= 1) {
            s += __shfl_down_sync(0xffffffffu, s, o);
            m = fmaxf(m, __shfl_down_sync(0xffffffffu, m, o));
        }
        if (lane == 0) {
            atomicAdd(&out[0], s);
            atomicMax(reinterpret_cast<int*>(&out[1]), __float_as_int(m));
        }
    }
}

// ---------------------------------------------------------------------------
// Trailing zero: restores the all-zero grid invariant for the next replay.
// ---------------------------------------------------------------------------
__global__ void k_zero() {
    int i = blockIdx.x * blockDim.x + threadIdx.x;  // 131072 threads
    float4* g4 = reinterpret_cast<float4*>(GRID_B);
    const float4 z = make_float4(0.f, 0.f, 0.f, 0.f);
#pragma unroll
    for (int k = 0; k < 4; ++k) g4[i + k * 131072] = z;
}

extern "C" void kernel_launch(void* const* d_in, const int* in_sizes, int n_in,
                              void* d_out, int out_size) {
    const float* pos = (const float*)d_in[0];
    const float* nsx = (const float*)d_in[1];
    const float* nsy = (const float*)d_in[2];
    const float* nsz = (const float*)d_in[3];
    float* out = (float*)d_out;

    k_scatter<<<(H_ + 255) / 256, 256>>>(pos, nsx, nsy, nsz, out);
    k_reduce<<<(NX_ * NY_) / 256, 256>>>(out);
    k_zero<<<512, 256>>>();
}

// round 9
// speedup vs baseline: 1.0790x; 1.0790x over previous
#include <cuda_runtime.h>
#include <math.h>

// ---------------------------------------------------------------------------
// ElectricOverflow. Grid 512x512x8 (8MB, L2-resident), padded both sides.
//
// Validated cost model (R2-R8): scatter cost ~ distinct 32B L2 sectors
// touched per (node, xy-cell), ~5.83/node avg — geometrically minimal under
// the z-major layout. Emission MUST NOT cross z-row sector boundaries
// (R5/R8's zbase trick inflated sectors ~25% -> regressions). 1 node/thread
// maximizes concurrency (2/thread dropped occupancy and regressed).
//
// Two launches only: [scatter, reduce+reset]. Device globals start zeroed;
// reduce stores zeros back after reading, restoring the replay invariant.
// Pads are never read and never reset (harmless accumulation).
// ---------------------------------------------------------------------------

#define NM_ 250000
#define NT_ 8000
#define NF_ 60000
#define N_  (NM_ + NT_ + NF_)    // 318000
#define NX_ 512
#define NY_ 512
#define NZ_ 8
#define NBINS_ (NX_ * NY_ * NZ_) // 2097152
#define PADF_ 4424               // covers ix/iy in [-1,512], z in [1,6]

#define SQRT2H 0.7071067811865476f
#define C1 0.41421356237309515f  // sqrt2 - 1
#define C2 0.5857864376269049f   // 2 - sqrt2

__device__ float g_pad[PADF_ + NBINS_ + PADF_];
#define GRID_B (g_pad + PADF_)

__device__ __forceinline__ void red1(float* p, float v) {
    asm volatile("red.global.add.f32 [%0], %1;" :: "l"(p), "f"(v) : "memory");
}
__device__ __forceinline__ void red2(float* p, float a, float b) {
    asm volatile("red.global.add.v2.f32 [%0], {%1, %2};"
                 :: "l"(p), "f"(a), "f"(b) : "memory");
}

// Emit up to 3 z-lane REDs, pairing adjacent surviving lanes when 8B-aligned.
// Never crosses the 32B z-row sector.
__device__ __forceinline__ void emit_z(float* p, float wxy,
                                       float v0, float v1, float v2,
                                       bool e0, bool e1, bool e2, bool even0) {
    if (e0 && e1 && even0) {
        red2(p, wxy * v0, wxy * v1);
        if (e2) red1(p + 2, wxy * v2);
    } else {
        if (e0) red1(p, wxy * v0);
        if (e1 && e2 && !even0) red2(p + 1, wxy * v1, wxy * v2);
        else {
            if (e1) red1(p + 1, wxy * v1);
            if (e2) red1(p + 2, wxy * v2);
        }
    }
}

// ---------------------------------------------------------------------------
// Fused scatter (1 node/thread). Threads [0, NM+NF): movable+fixed (clamped
// size sqrt2^3, centered, weight = volume ratio). Threads [NM+NF, N): fillers.
// z-border lanes culled (reference overwrites border bins with 1.0);
// x/y out-of-range lanes alias into padding (never read).
// Thread 0 seeds the outputs (reduce consumes them after).
// ---------------------------------------------------------------------------
__global__ void k_scatter(const float* __restrict__ pos,
                          const float* __restrict__ nsx,
                          const float* __restrict__ nsy,
                          const float* __restrict__ nsz,
                          float* __restrict__ out) {
    int t = blockIdx.x * blockDim.x + threadIdx.x;
    if (t >= N_) return;
    if (t == 0) { out[0] = 0.0f; out[1] = 1.0f; }   // border density = 1.0

    bool isFill = (t >= NM_ + NF_);
    int j = isFill ? (t - NF_) : ((t < NM_) ? t : (t + NT_));

    float sx = nsx[j], sy = nsy[j], sz = nsz[j];
    float px = pos[j], py = pos[N_ + j], pz = pos[2 * N_ + j];

    if (!isFill) {
        const float w = sx * sy * sz * 0.35355339059327373f;  // /(2*sqrt2)
        float x0 = px + 0.5f * sx - SQRT2H;
        float y0 = py + 0.5f * sy - SQRT2H;
        float z0 = pz + 0.5f * sz - SQRT2H;

        float fxf = floorf(x0), fyf = floorf(y0), fzf = floorf(z0);
        int ix0 = (int)fxf, iy0 = (int)fyf, iz0 = (int)fzf;
        float fx = x0 - fxf, fy = y0 - fyf, fz = z0 - fzf;

        float ox[3] = { 1.0f - fx, fminf(fx + C1, 1.0f), fmaxf(fx - C2, 0.0f) };
        float oy[3] = { 1.0f - fy, fminf(fy + C1, 1.0f), fmaxf(fy - C2, 0.0f) };

        float v0 = 1.0f - fz;
        float v1 = fminf(fz + C1, 1.0f);
        float v2 = fmaxf(fz - C2, 0.0f);
        bool e0 = (iz0 >= 1) & (iz0 <= 6);
        bool e1 = (iz0 >= 0) & (iz0 <= 5);
        bool e2 = (iz0 >= -1) & (iz0 <= 4) & (v2 > 0.0f);
        if (!(e0 | e1 | e2)) return;
        bool even0 = ((iz0 & 1) == 0);

#pragma unroll
        for (int a = 0; a < 3; ++a) {
            if (ox[a] == 0.0f) continue;          // only a==2 can be 0
            float wx = w * ox[a];
#pragma unroll
            for (int b = 0; b < 3; ++b) {
                if (oy[b] == 0.0f) continue;
                float* p = GRID_B + (((ix0 + a) * NY_ + (iy0 + b)) << 3) + iz0;
                emit_z(p, wx * oy[b], v0, v1, v2, e0, e1, e2, even0);
            }
        }
    } else {
        float fxf = floorf(px), fyf = floorf(py), fzf = floorf(pz);
        int ix0 = (int)fxf, iy0 = (int)fyf, iz0 = (int)fzf;  // iz0 in [0,6]
        float fx = px - fxf, fy = py - fyf, fz = pz - fzf;

        float ox[2] = { fminf(1.0f - fx, sx), fmaxf(fx + sx - 1.0f, 0.0f) };
        float oy[2] = { fminf(1.0f - fy, sy), fmaxf(fy + sy - 1.0f, 0.0f) };
        float v0 = fminf(1.0f - fz, sz);
        float v1 = fmaxf(fz + sz - 1.0f, 0.0f);
        bool e0 = (iz0 >= 1);
        bool e1 = (iz0 <= 5) & (v1 > 0.0f);
        if (!(e0 | e1)) return;
        bool even0 = ((iz0 & 1) == 0);

#pragma unroll
        for (int a = 0; a < 2; ++a) {
            if (ox[a] == 0.0f) continue;
#pragma unroll
            for (int b = 0; b < 2; ++b) {
                if (oy[b] == 0.0f) continue;
                float wxy = ox[a] * oy[b];
                float* p = GRID_B + (((ix0 + a) * NY_ + (iy0 + b)) << 3) + iz0;
                if (e0 && e1 && even0) red2(p, wxy * v0, wxy * v1);
                else {
                    if (e0) red1(p, wxy * v0);
                    if (e1) red1(p + 1, wxy * v1);
                }
            }
        }
    }
}

// ---------------------------------------------------------------------------
// Reduction WITH RESET: one thread per (x,y) z-row. Loads 2x float4,
// immediately stores zeros back (grid pristine for the next replay),
// reduces interior z=1..6 of interior rows. Grid is L2-warm in the timed
// graph, so the extra store stream is cheap (R5's 16.9us was a cold-ncu
// artifact: 8MB DRAM miss stream).
// ---------------------------------------------------------------------------
__global__ void k_reduce(float* __restrict__ out) {
    int t = blockIdx.x * blockDim.x + threadIdx.x;  // 512*512 threads
    float4* g4 = reinterpret_cast<float4*>(GRID_B) + t * 2;
    float4 a = g4[0];
    float4 b = g4[1];
    const float4 z = make_float4(0.f, 0.f, 0.f, 0.f);
    g4[0] = z;
    g4[1] = z;

    float s = 0.0f, m = 0.0f;
    int ix = t >> 9;
    int iy = t & 511;
    if (ix >= 1 && ix <= NX_ - 2 && iy >= 1 && iy <= NY_ - 2) {
        s = fmaxf(a.y - 1.0f, 0.0f) + fmaxf(a.z - 1.0f, 0.0f) +
            fmaxf(a.w - 1.0f, 0.0f) + fmaxf(b.x - 1.0f, 0.0f) +
            fmaxf(b.y - 1.0f, 0.0f) + fmaxf(b.z - 1.0f, 0.0f);
        m = fmaxf(fmaxf(fmaxf(a.y, a.z), fmaxf(a.w, b.x)), fmaxf(b.y, b.z));
    }
#pragma unroll
    for (int o = 16; o > 0; o >>= 1) {
        s += __shfl_down_sync(0xffffffffu, s, o);
        m = fmaxf(m, __shfl_down_sync(0xffffffffu, m, o));
    }
    __shared__ float ss[8], sm[8];
    int lane = threadIdx.x & 31;
    int wid = threadIdx.x >> 5;
    if (lane == 0) { ss[wid] = s; sm[wid] = m; }
    __syncthreads();
    if (wid == 0) {
        int nw = blockDim.x >> 5;
        s = (lane < nw) ? ss[lane] : 0.0f;
        m = (lane < nw) ? sm[lane] : 0.0f;
#pragma unroll
        for (int o = 4; o > 0; o >>= 1) {
            s += __shfl_down_sync(0xffffffffu, s, o);
            m = fmaxf(m, __shfl_down_sync(0xffffffffu, m, o));
        }
        if (lane == 0) {
            atomicAdd(&out[0], s);
            atomicMax(reinterpret_cast<int*>(&out[1]), __float_as_int(m));
        }
    }
}

extern "C" void kernel_launch(void* const* d_in, const int* in_sizes, int n_in,
                              void* d_out, int out_size) {
    const float* pos = (const float*)d_in[0];
    const float* nsx = (const float*)d_in[1];
    const float* nsy = (const float*)d_in[2];
    const float* nsz = (const float*)d_in[3];
    float* out = (float*)d_out;

    k_scatter<<<(N_ + 255) / 256, 256>>>(pos, nsx, nsy, nsz, out);
    k_reduce<<<(NX_ * NY_) / 256, 256>>>(out);
}

// round 10
// speedup vs baseline: 1.0826x; 1.0033x over previous
#include <cuda_runtime.h>
#include <math.h>

// ---------------------------------------------------------------------------
// ElectricOverflow. Grid 512x512x8 (8MB, L2-resident), padded both sides.
//
// Locked-in findings (R2-R9):
//  * Scatter cost = distinct 32B L2 sectors touched (~5.83/node) — at the
//    LTS atomic floor (~61% SOL); lane/instruction variants all neutral.
//    Emission must never cross a z-row sector (R5/R8 regressions).
//  * 1 node/thread (in-thread serialization regressed, R8).
//  * 3 launches [scatter, reduce, zero] beat reduce-with-reset (R5, R9).
//  * Gather/binning rewrite computed to ~70us of SM issue — rejected.
// This round: finer scatter blocks (128) for wave balance; 2-thread/row
// reduce for latency.
// ---------------------------------------------------------------------------

#define NM_ 250000
#define NT_ 8000
#define NF_ 60000
#define N_  (NM_ + NT_ + NF_)    // 318000
#define NX_ 512
#define NY_ 512
#define NZ_ 8
#define NBINS_ (NX_ * NY_ * NZ_) // 2097152
#define PADF_ 4424               // covers ix/iy in [-1,512], z in [1,6]

#define SQRT2H 0.7071067811865476f
#define C1 0.41421356237309515f  // sqrt2 - 1
#define C2 0.5857864376269049f   // 2 - sqrt2

__device__ float g_pad[PADF_ + NBINS_ + PADF_];
#define GRID_B (g_pad + PADF_)

__device__ __forceinline__ void red1(float* p, float v) {
    asm volatile("red.global.add.f32 [%0], %1;" :: "l"(p), "f"(v) : "memory");
}
__device__ __forceinline__ void red2(float* p, float a, float b) {
    asm volatile("red.global.add.v2.f32 [%0], {%1, %2};"
                 :: "l"(p), "f"(a), "f"(b) : "memory");
}

// Emit up to 3 z-lane REDs, pairing adjacent surviving lanes when 8B-aligned.
// Never crosses the 32B z-row sector.
__device__ __forceinline__ void emit_z(float* p, float wxy,
                                       float v0, float v1, float v2,
                                       bool e0, bool e1, bool e2, bool even0) {
    if (e0 && e1 && even0) {
        red2(p, wxy * v0, wxy * v1);
        if (e2) red1(p + 2, wxy * v2);
    } else {
        if (e0) red1(p, wxy * v0);
        if (e1 && e2 && !even0) red2(p + 1, wxy * v1, wxy * v2);
        else {
            if (e1) red1(p + 1, wxy * v1);
            if (e2) red1(p + 2, wxy * v2);
        }
    }
}

// ---------------------------------------------------------------------------
// Fused scatter (1 node/thread, 128-thread blocks for fine wave balance).
// ---------------------------------------------------------------------------
__global__ void k_scatter(const float* __restrict__ pos,
                          const float* __restrict__ nsx,
                          const float* __restrict__ nsy,
                          const float* __restrict__ nsz,
                          float* __restrict__ out) {
    int t = blockIdx.x * blockDim.x + threadIdx.x;
    if (t >= N_) return;
    if (t == 0) { out[0] = 0.0f; out[1] = 1.0f; }   // border density = 1.0

    bool isFill = (t >= NM_ + NF_);
    int j = isFill ? (t - NF_) : ((t < NM_) ? t : (t + NT_));

    float sx = nsx[j], sy = nsy[j], sz = nsz[j];
    float px = pos[j], py = pos[N_ + j], pz = pos[2 * N_ + j];

    if (!isFill) {
        const float w = sx * sy * sz * 0.35355339059327373f;  // /(2*sqrt2)
        float x0 = px + 0.5f * sx - SQRT2H;
        float y0 = py + 0.5f * sy - SQRT2H;
        float z0 = pz + 0.5f * sz - SQRT2H;

        float fxf = floorf(x0), fyf = floorf(y0), fzf = floorf(z0);
        int ix0 = (int)fxf, iy0 = (int)fyf, iz0 = (int)fzf;
        float fx = x0 - fxf, fy = y0 - fyf, fz = z0 - fzf;

        float ox[3] = { 1.0f - fx, fminf(fx + C1, 1.0f), fmaxf(fx - C2, 0.0f) };
        float oy[3] = { 1.0f - fy, fminf(fy + C1, 1.0f), fmaxf(fy - C2, 0.0f) };

        float v0 = 1.0f - fz;
        float v1 = fminf(fz + C1, 1.0f);
        float v2 = fmaxf(fz - C2, 0.0f);
        bool e0 = (iz0 >= 1) & (iz0 <= 6);
        bool e1 = (iz0 >= 0) & (iz0 <= 5);
        bool e2 = (iz0 >= -1) & (iz0 <= 4) & (v2 > 0.0f);
        if (!(e0 | e1 | e2)) return;
        bool even0 = ((iz0 & 1) == 0);

#pragma unroll
        for (int a = 0; a < 3; ++a) {
            if (ox[a] == 0.0f) continue;          // only a==2 can be 0
            float wx = w * ox[a];
#pragma unroll
            for (int b = 0; b < 3; ++b) {
                if (oy[b] == 0.0f) continue;
                float* p = GRID_B + (((ix0 + a) * NY_ + (iy0 + b)) << 3) + iz0;
                emit_z(p, wx * oy[b], v0, v1, v2, e0, e1, e2, even0);
            }
        }
    } else {
        float fxf = floorf(px), fyf = floorf(py), fzf = floorf(pz);
        int ix0 = (int)fxf, iy0 = (int)fyf, iz0 = (int)fzf;  // iz0 in [0,6]
        float fx = px - fxf, fy = py - fyf, fz = pz - fzf;

        float ox[2] = { fminf(1.0f - fx, sx), fmaxf(fx + sx - 1.0f, 0.0f) };
        float oy[2] = { fminf(1.0f - fy, sy), fmaxf(fy + sy - 1.0f, 0.0f) };
        float v0 = fminf(1.0f - fz, sz);
        float v1 = fmaxf(fz + sz - 1.0f, 0.0f);
        bool e0 = (iz0 >= 1);
        bool e1 = (iz0 <= 5) & (v1 > 0.0f);
        if (!(e0 | e1)) return;
        bool even0 = ((iz0 & 1) == 0);

#pragma unroll
        for (int a = 0; a < 2; ++a) {
            if (ox[a] == 0.0f) continue;
#pragma unroll
            for (int b = 0; b < 2; ++b) {
                if (oy[b] == 0.0f) continue;
                float wxy = ox[a] * oy[b];
                float* p = GRID_B + (((ix0 + a) * NY_ + (iy0 + b)) << 3) + iz0;
                if (e0 && e1 && even0) red2(p, wxy * v0, wxy * v1);
                else {
                    if (e0) red1(p, wxy * v0);
                    if (e1) red1(p + 1, wxy * v1);
                }
            }
        }
    }
}

// ---------------------------------------------------------------------------
// Reduction (load-only): 2 threads per (x,y) z-row, one float4 each.
// Half h=0 covers z0..3 (interior z1..3), h=1 covers z4..7 (interior z4..6).
// Border rows skipped (cost 0; max floor 1.0 seeded in k_scatter).
// ---------------------------------------------------------------------------
__global__ void k_reduce(float* __restrict__ out) {
    int t = blockIdx.x * blockDim.x + threadIdx.x;  // 2 * 512*512 threads
    int r = t >> 1;            // row id
    int h = t & 1;             // which half of the z-row
    float s = 0.0f, m = 0.0f;
    int ix = r >> 9;
    int iy = r & 511;
    if (ix >= 1 && ix <= NX_ - 2 && iy >= 1 && iy <= NY_ - 2) {
        float4 a = reinterpret_cast<const float4*>(GRID_B)[t];
        // h=0: lanes z0..z3 -> interior y,z,w ; h=1: lanes z4..z7 -> x,y,z
        float u0 = h ? a.x : a.y;
        float u1 = h ? a.y : a.z;
        float u2 = h ? a.z : a.w;
        s = fmaxf(u0 - 1.0f, 0.0f) + fmaxf(u1 - 1.0f, 0.0f) +
            fmaxf(u2 - 1.0f, 0.0f);
        m = fmaxf(fmaxf(u0, u1), u2);
    }
#pragma unroll
    for (int o = 16; o > 0; o >>= 1) {
        s += __shfl_down_sync(0xffffffffu, s, o);
        m = fmaxf(m, __shfl_down_sync(0xffffffffu, m, o));
    }
    __shared__ float ss[8], sm[8];
    int lane = threadIdx.x & 31;
    int wid = threadIdx.x >> 5;
    if (lane == 0) { ss[wid] = s; sm[wid] = m; }
    __syncthreads();
    if (wid == 0) {
        int nw = blockDim.x >> 5;
        s = (lane < nw) ? ss[lane] : 0.0f;
        m = (lane < nw) ? sm[lane] : 0.0f;
#pragma unroll
        for (int o = 4; o > 0; o >>= 1) {
            s += __shfl_down_sync(0xffffffffu, s, o);
            m = fmaxf(m, __shfl_down_sync(0xffffffffu, m, o));
        }
        if (lane == 0) {
            atomicAdd(&out[0], s);
            atomicMax(reinterpret_cast<int*>(&out[1]), __float_as_int(m));
        }
    }
}

// ---------------------------------------------------------------------------
// Trailing zero: restores the all-zero grid invariant for the next replay.
// ---------------------------------------------------------------------------
__global__ void k_zero() {
    int i = blockIdx.x * blockDim.x + threadIdx.x;  // 524288 threads
    reinterpret_cast<float4*>(GRID_B)[i] = make_float4(0.f, 0.f, 0.f, 0.f);
}

extern "C" void kernel_launch(void* const* d_in, const int* in_sizes, int n_in,
                              void* d_out, int out_size) {
    const float* pos = (const float*)d_in[0];
    const float* nsx = (const float*)d_in[1];
    const float* nsy = (const float*)d_in[2];
    const float* nsz = (const float*)d_in[3];
    float* out = (float*)d_out;

    k_scatter<<<(N_ + 127) / 128, 128>>>(pos, nsx, nsy, nsz, out);
    k_reduce<<<(2 * NX_ * NY_) / 256, 256>>>(out);
    k_zero<<<2048, 256>>>();
}

// round 11
// speedup vs baseline: 1.1606x; 1.0720x over previous
#include <cuda_runtime.h>
#include <math.h>
#include <stdint.h>

// ---------------------------------------------------------------------------
// ElectricOverflow. Grid 512x512x8 (8MB, L2-resident), padded both sides.
//
// Locked-in findings (R2-R10):
//  * Scatter is pinned at ~20us across 5 variants (lanes/instr/pairing/ILP/
//    block size) -> hard LTS/LSU wall; R4 emission kept as-is.
//  * 3 launches [zero, scatter, reduce] is the best structure (R4 = 27.07).
//  * k_zero was STG.128-issue-cost bound (~3542 st/SM x ~3cyc = 4.9us).
//    This round: bulk-TMA zero — 64 blocks zero 32KB smem once, each issues
//    4 single-instruction 32KB cp.async.bulk stores -> 8MB at TMA rate.
// ---------------------------------------------------------------------------

#define NM_ 250000
#define NT_ 8000
#define NF_ 60000
#define N_  (NM_ + NT_ + NF_)    // 318000
#define NX_ 512
#define NY_ 512
#define NZ_ 8
#define NBINS_ (NX_ * NY_ * NZ_) // 2097152
#define PADF_ 4424               // covers ix/iy in [-1,512], z in [1,6]; 16B-mult

#define SQRT2H 0.7071067811865476f
#define C1 0.41421356237309515f  // sqrt2 - 1
#define C2 0.5857864376269049f   // 2 - sqrt2

__device__ __align__(128) float g_pad[PADF_ + NBINS_ + PADF_];
#define GRID_B (g_pad + PADF_)

__device__ __forceinline__ void red1(float* p, float v) {
    asm volatile("red.global.add.f32 [%0], %1;" :: "l"(p), "f"(v) : "memory");
}
__device__ __forceinline__ void red2(float* p, float a, float b) {
    asm volatile("red.global.add.v2.f32 [%0], {%1, %2};"
                 :: "l"(p), "f"(a), "f"(b) : "memory");
}

// ---------------------------------------------------------------------------
// Bulk-TMA zero: 64 blocks. Each zeroes a 32KB smem buffer (256thr x 8
// STS.128 — trivial issue cost), then one elected thread fires 4x 32KB
// cp.async.bulk shared->global stores. 256 bulk ops cover the 8MB grid at
// the chip TMA/LTS write rate instead of 524k STG.128 issue slots.
// ---------------------------------------------------------------------------
#define ZERO_BLOCKS 64
#define ZCHUNK 32768                       // bytes per bulk store
#define ZPER_BLOCK 4                       // 64 * 4 * 32KB = 8MB

__global__ void k_zero(float* __restrict__ out) {
    __shared__ __align__(128) float zbuf[ZCHUNK / 4];
    int tid = threadIdx.x;
    float4* s4 = reinterpret_cast<float4*>(zbuf);
    const float4 z = make_float4(0.f, 0.f, 0.f, 0.f);
#pragma unroll
    for (int k = 0; k < (ZCHUNK / 16) / 256; ++k)   // 8 iters
        s4[tid + k * 256] = z;
    __syncthreads();
    asm volatile("fence.proxy.async.shared::cta;" ::: "memory");

    if (tid == 0) {
        uint32_t saddr;
        asm("{ .reg .u64 t; cvta.to.shared.u64 t, %1; cvt.u32.u64 %0, t; }"
            : "=r"(saddr) : "l"(zbuf));
        char* gbase = reinterpret_cast<char*>(GRID_B) +
                      (size_t)blockIdx.x * (ZPER_BLOCK * ZCHUNK);
#pragma unroll
        for (int k = 0; k < ZPER_BLOCK; ++k) {
            asm volatile(
                "cp.async.bulk.global.shared::cta.bulk_group [%0], [%1], %2;"
                :: "l"(gbase + k * ZCHUNK), "r"(saddr), "n"(ZCHUNK)
                : "memory");
        }
        asm volatile("cp.async.bulk.commit_group;" ::: "memory");
        asm volatile("cp.async.bulk.wait_group 0;" ::: "memory");
    }
    if (blockIdx.x == 0 && tid == 0) { out[0] = 0.0f; out[1] = 1.0f; }
}

// Emit up to 3 z-lane REDs, pairing adjacent surviving lanes when 8B-aligned.
// Never crosses the 32B z-row sector.
__device__ __forceinline__ void emit_z(float* p, float wxy,
                                       float v0, float v1, float v2,
                                       bool e0, bool e1, bool e2, bool even0) {
    if (e0 && e1 && even0) {
        red2(p, wxy * v0, wxy * v1);
        if (e2) red1(p + 2, wxy * v2);
    } else {
        if (e0) red1(p, wxy * v0);
        if (e1 && e2 && !even0) red2(p + 1, wxy * v1, wxy * v2);
        else {
            if (e1) red1(p + 1, wxy * v1);
            if (e2) red1(p + 2, wxy * v2);
        }
    }
}

// ---------------------------------------------------------------------------
// Fused scatter (1 node/thread, 256-thread blocks — R4 champion config).
// ---------------------------------------------------------------------------
__global__ void k_scatter(const float* __restrict__ pos,
                          const float* __restrict__ nsx,
                          const float* __restrict__ nsy,
                          const float* __restrict__ nsz) {
    int t = blockIdx.x * blockDim.x + threadIdx.x;
    if (t >= N_) return;

    bool isFill = (t >= NM_ + NF_);
    int j = isFill ? (t - NF_) : ((t < NM_) ? t : (t + NT_));

    float sx = nsx[j], sy = nsy[j], sz = nsz[j];
    float px = pos[j], py = pos[N_ + j], pz = pos[2 * N_ + j];

    if (!isFill) {
        const float w = sx * sy * sz * 0.35355339059327373f;  // /(2*sqrt2)
        float x0 = px + 0.5f * sx - SQRT2H;
        float y0 = py + 0.5f * sy - SQRT2H;
        float z0 = pz + 0.5f * sz - SQRT2H;

        float fxf = floorf(x0), fyf = floorf(y0), fzf = floorf(z0);
        int ix0 = (int)fxf, iy0 = (int)fyf, iz0 = (int)fzf;
        float fx = x0 - fxf, fy = y0 - fyf, fz = z0 - fzf;

        float ox[3] = { 1.0f - fx, fminf(fx + C1, 1.0f), fmaxf(fx - C2, 0.0f) };
        float oy[3] = { 1.0f - fy, fminf(fy + C1, 1.0f), fmaxf(fy - C2, 0.0f) };

        float v0 = 1.0f - fz;
        float v1 = fminf(fz + C1, 1.0f);
        float v2 = fmaxf(fz - C2, 0.0f);
        bool e0 = (iz0 >= 1) & (iz0 <= 6);
        bool e1 = (iz0 >= 0) & (iz0 <= 5);
        bool e2 = (iz0 >= -1) & (iz0 <= 4) & (v2 > 0.0f);
        if (!(e0 | e1 | e2)) return;
        bool even0 = ((iz0 & 1) == 0);

#pragma unroll
        for (int a = 0; a < 3; ++a) {
            if (ox[a] == 0.0f) continue;          // only a==2 can be 0
            float wx = w * ox[a];
#pragma unroll
            for (int b = 0; b < 3; ++b) {
                if (oy[b] == 0.0f) continue;
                float* p = GRID_B + (((ix0 + a) * NY_ + (iy0 + b)) << 3) + iz0;
                emit_z(p, wx * oy[b], v0, v1, v2, e0, e1, e2, even0);
            }
        }
    } else {
        float fxf = floorf(px), fyf = floorf(py), fzf = floorf(pz);
        int ix0 = (int)fxf, iy0 = (int)fyf, iz0 = (int)fzf;  // iz0 in [0,6]
        float fx = px - fxf, fy = py - fyf, fz = pz - fzf;

        float ox[2] = { fminf(1.0f - fx, sx), fmaxf(fx + sx - 1.0f, 0.0f) };
        float oy[2] = { fminf(1.0f - fy, sy), fmaxf(fy + sy - 1.0f, 0.0f) };
        float v0 = fminf(1.0f - fz, sz);
        float v1 = fmaxf(fz + sz - 1.0f, 0.0f);
        bool e0 = (iz0 >= 1);
        bool e1 = (iz0 <= 5) & (v1 > 0.0f);
        if (!(e0 | e1)) return;
        bool even0 = ((iz0 & 1) == 0);

#pragma unroll
        for (int a = 0; a < 2; ++a) {
            if (ox[a] == 0.0f) continue;
#pragma unroll
            for (int b = 0; b < 2; ++b) {
                if (oy[b] == 0.0f) continue;
                float wxy = ox[a] * oy[b];
                float* p = GRID_B + (((ix0 + a) * NY_ + (iy0 + b)) << 3) + iz0;
                if (e0 && e1 && even0) red2(p, wxy * v0, wxy * v1);
                else {
                    if (e0) red1(p, wxy * v0);
                    if (e1) red1(p + 1, wxy * v1);
                }
            }
        }
    }
}

// ---------------------------------------------------------------------------
// Reduction (load-only): one thread per (x,y) z-row, 2x float4, interior
// z=1..6. Border rows skipped (cost 0; max floor 1.0 seeded in k_zero).
// ---------------------------------------------------------------------------
__global__ void k_reduce(float* __restrict__ out) {
    int t = blockIdx.x * blockDim.x + threadIdx.x;  // 512*512 threads
    float s = 0.0f, m = 0.0f;
    int ix = t >> 9;
    int iy = t & 511;
    if (ix >= 1 && ix <= NX_ - 2 && iy >= 1 && iy <= NY_ - 2) {
        const float4* g4 = reinterpret_cast<const float4*>(GRID_B) + t * 2;
        float4 a = g4[0];
        float4 b = g4[1];
        s = fmaxf(a.y - 1.0f, 0.0f) + fmaxf(a.z - 1.0f, 0.0f) +
            fmaxf(a.w - 1.0f, 0.0f) + fmaxf(b.x - 1.0f, 0.0f) +
            fmaxf(b.y - 1.0f, 0.0f) + fmaxf(b.z - 1.0f, 0.0f);
        m = fmaxf(fmaxf(fmaxf(a.y, a.z), fmaxf(a.w, b.x)), fmaxf(b.y, b.z));
    }
#pragma unroll
    for (int o = 16; o > 0; o >>= 1) {
        s += __shfl_down_sync(0xffffffffu, s, o);
        m = fmaxf(m, __shfl_down_sync(0xffffffffu, m, o));
    }
    __shared__ float ss[8], sm[8];
    int lane = threadIdx.x & 31;
    int wid = threadIdx.x >> 5;
    if (lane == 0) { ss[wid] = s; sm[wid] = m; }
    __syncthreads();
    if (wid == 0) {
        int nw = blockDim.x >> 5;
        s = (lane < nw) ? ss[lane] : 0.0f;
        m = (lane < nw) ? sm[lane] : 0.0f;
#pragma unroll
        for (int o = 4; o > 0; o >>= 1) {
            s += __shfl_down_sync(0xffffffffu, s, o);
            m = fmaxf(m, __shfl_down_sync(0xffffffffu, m, o));
        }
        if (lane == 0) {
            atomicAdd(&out[0], s);
            atomicMax(reinterpret_cast<int*>(&out[1]), __float_as_int(m));
        }
    }
}

extern "C" void kernel_launch(void* const* d_in, const int* in_sizes, int n_in,
                              void* d_out, int out_size) {
    const float* pos = (const float*)d_in[0];
    const float* nsx = (const float*)d_in[1];
    const float* nsy = (const float*)d_in[2];
    const float* nsz = (const float*)d_in[3];
    float* out = (float*)d_out;

    k_zero<<<ZERO_BLOCKS, 256>>>(out);
    k_scatter<<<(N_ + 255) / 256, 256>>>(pos, nsx, nsy, nsz);
    k_reduce<<<(NX_ * NY_) / 256, 256>>>(out);
}

// round 12
// speedup vs baseline: 1.2554x; 1.0817x over previous
#include <cuda_runtime.h>
#include <math.h>
#include <stdint.h>

// ---------------------------------------------------------------------------
// ElectricOverflow. Grid 512x512x8 (8MB, L2-resident), padded both sides.
//
// Locked-in findings (R2-R11):
//  * Scatter pinned ~20us(ncu)/~17us(real) across 6 variants -> LTS wall.
//  * ncu per-kernel durations carry a ~4us floor (k_noop=4.0us) — the real
//    tail is launch-boundary serialization, not store work.
//  * Structure [zero, scatter, reduce] with R4 kernels = 27.07us champion.
// This round: PDL. Dependents launch early and run their prologue (input
// loads, window math, ramp) under the predecessor; cudaGridDependency-
// Synchronize() guards the actual memory dependency (first RED / first load).
// ---------------------------------------------------------------------------

#define NM_ 250000
#define NT_ 8000
#define NF_ 60000
#define N_  (NM_ + NT_ + NF_)    // 318000
#define NX_ 512
#define NY_ 512
#define NZ_ 8
#define NBINS_ (NX_ * NY_ * NZ_) // 2097152
#define PADF_ 4424               // covers ix/iy in [-1,512], z in [1,6]

#define SQRT2H 0.7071067811865476f
#define C1 0.41421356237309515f  // sqrt2 - 1
#define C2 0.5857864376269049f   // 2 - sqrt2

__device__ __align__(128) float g_pad[PADF_ + NBINS_ + PADF_];
#define GRID_B (g_pad + PADF_)

__device__ __forceinline__ void red1(float* p, float v) {
    asm volatile("red.global.add.f32 [%0], %1;" :: "l"(p), "f"(v) : "memory");
}
__device__ __forceinline__ void red2(float* p, float a, float b) {
    asm volatile("red.global.add.v2.f32 [%0], {%1, %2};"
                 :: "l"(p), "f"(a), "f"(b) : "memory");
}

// ---------------------------------------------------------------------------
// Zero (R4-proven): 512 blocks x 256 thr x 4 float4, coalesced; leaves the
// grid dirty in L2. Releases the dependent scatter early via PDL trigger.
// ---------------------------------------------------------------------------
__global__ void k_zero(float* __restrict__ out) {
    int i = blockIdx.x * blockDim.x + threadIdx.x;  // 131072 threads
    float4* g4 = reinterpret_cast<float4*>(GRID_B);
    const float4 z = make_float4(0.f, 0.f, 0.f, 0.f);
#pragma unroll
    for (int k = 0; k < 4; ++k) g4[i + k * 131072] = z;
    if (i == 0) { out[0] = 0.0f; out[1] = 1.0f; }   // border density = 1.0
    cudaTriggerProgrammaticLaunchCompletion();
}

// Emit up to 3 z-lane REDs, pairing adjacent surviving lanes when 8B-aligned.
// Never crosses the 32B z-row sector.
__device__ __forceinline__ void emit_z(float* p, float wxy,
                                       float v0, float v1, float v2,
                                       bool e0, bool e1, bool e2, bool even0) {
    if (e0 && e1 && even0) {
        red2(p, wxy * v0, wxy * v1);
        if (e2) red1(p + 2, wxy * v2);
    } else {
        if (e0) red1(p, wxy * v0);
        if (e1 && e2 && !even0) red2(p + 1, wxy * v1, wxy * v2);
        else {
            if (e1) red1(p + 1, wxy * v1);
            if (e2) red1(p + 2, wxy * v2);
        }
    }
}

// ---------------------------------------------------------------------------
// Fused scatter (1 node/thread, 256-thr blocks — champion config).
// PDL: all input loads + window math run BEFORE cudaGridDependency-
// Synchronize(); only the REDs wait for k_zero's completion.
// ---------------------------------------------------------------------------
__global__ void k_scatter(const float* __restrict__ pos,
                          const float* __restrict__ nsx,
                          const float* __restrict__ nsy,
                          const float* __restrict__ nsz) {
    int t = blockIdx.x * blockDim.x + threadIdx.x;
    if (t >= N_) {
        cudaGridDependencySynchronize();
        return;
    }

    bool isFill = (t >= NM_ + NF_);
    int j = isFill ? (t - NF_) : ((t < NM_) ? t : (t + NT_));

    float sx = nsx[j], sy = nsy[j], sz = nsz[j];
    float px = pos[j], py = pos[N_ + j], pz = pos[2 * N_ + j];

    if (!isFill) {
        const float w = sx * sy * sz * 0.35355339059327373f;  // /(2*sqrt2)
        float x0 = px + 0.5f * sx - SQRT2H;
        float y0 = py + 0.5f * sy - SQRT2H;
        float z0 = pz + 0.5f * sz - SQRT2H;

        float fxf = floorf(x0), fyf = floorf(y0), fzf = floorf(z0);
        int ix0 = (int)fxf, iy0 = (int)fyf, iz0 = (int)fzf;
        float fx = x0 - fxf, fy = y0 - fyf, fz = z0 - fzf;

        float ox[3] = { 1.0f - fx, fminf(fx + C1, 1.0f), fmaxf(fx - C2, 0.0f) };
        float oy[3] = { 1.0f - fy, fminf(fy + C1, 1.0f), fmaxf(fy - C2, 0.0f) };

        float v0 = 1.0f - fz;
        float v1 = fminf(fz + C1, 1.0f);
        float v2 = fmaxf(fz - C2, 0.0f);
        bool e0 = (iz0 >= 1) & (iz0 <= 6);
        bool e1 = (iz0 >= 0) & (iz0 <= 5);
        bool e2 = (iz0 >= -1) & (iz0 <= 4) & (v2 > 0.0f);
        bool even0 = ((iz0 & 1) == 0);

        cudaGridDependencySynchronize();       // wait for zero'd grid
        if (!(e0 | e1 | e2)) return;

#pragma unroll
        for (int a = 0; a < 3; ++a) {
            if (ox[a] == 0.0f) continue;          // only a==2 can be 0
            float wx = w * ox[a];
#pragma unroll
            for (int b = 0; b < 3; ++b) {
                if (oy[b] == 0.0f) continue;
                float* p = GRID_B + (((ix0 + a) * NY_ + (iy0 + b)) << 3) + iz0;
                emit_z(p, wx * oy[b], v0, v1, v2, e0, e1, e2, even0);
            }
        }
    } else {
        float fxf = floorf(px), fyf = floorf(py), fzf = floorf(pz);
        int ix0 = (int)fxf, iy0 = (int)fyf, iz0 = (int)fzf;  // iz0 in [0,6]
        float fx = px - fxf, fy = py - fyf, fz = pz - fzf;

        float ox[2] = { fminf(1.0f - fx, sx), fmaxf(fx + sx - 1.0f, 0.0f) };
        float oy[2] = { fminf(1.0f - fy, sy), fmaxf(fy + sy - 1.0f, 0.0f) };
        float v0 = fminf(1.0f - fz, sz);
        float v1 = fmaxf(fz + sz - 1.0f, 0.0f);
        bool e0 = (iz0 >= 1);
        bool e1 = (iz0 <= 5) & (v1 > 0.0f);
        bool even0 = ((iz0 & 1) == 0);

        cudaGridDependencySynchronize();       // wait for zero'd grid
        if (!(e0 | e1)) return;

#pragma unroll
        for (int a = 0; a < 2; ++a) {
            if (ox[a] == 0.0f) continue;
#pragma unroll
            for (int b = 0; b < 2; ++b) {
                if (oy[b] == 0.0f) continue;
                float wxy = ox[a] * oy[b];
                float* p = GRID_B + (((ix0 + a) * NY_ + (iy0 + b)) << 3) + iz0;
                if (e0 && e1 && even0) red2(p, wxy * v0, wxy * v1);
                else {
                    if (e0) red1(p, wxy * v0);
                    if (e1) red1(p + 1, wxy * v1);
                }
            }
        }
    }
    cudaTriggerProgrammaticLaunchCompletion();
}

// ---------------------------------------------------------------------------
// Reduction (load-only, champion config): one thread per (x,y) z-row,
// 2x float4, interior z=1..6. PDL: index math pre-sync; loads post-sync.
// ---------------------------------------------------------------------------
__global__ void k_reduce(float* __restrict__ out) {
    int t = blockIdx.x * blockDim.x + threadIdx.x;  // 512*512 threads
    float s = 0.0f, m = 0.0f;
    int ix = t >> 9;
    int iy = t & 511;
    bool interior = (ix >= 1) & (ix <= NX_ - 2) & (iy >= 1) & (iy <= NY_ - 2);

    cudaGridDependencySynchronize();           // wait for scatter's REDs

    if (interior) {
        const float4* g4 = reinterpret_cast<const float4*>(GRID_B) + t * 2;
        float4 a = g4[0];
        float4 b = g4[1];
        s = fmaxf(a.y - 1.0f, 0.0f) + fmaxf(a.z - 1.0f, 0.0f) +
            fmaxf(a.w - 1.0f, 0.0f) + fmaxf(b.x - 1.0f, 0.0f) +
            fmaxf(b.y - 1.0f, 0.0f) + fmaxf(b.z - 1.0f, 0.0f);
        m = fmaxf(fmaxf(fmaxf(a.y, a.z), fmaxf(a.w, b.x)), fmaxf(b.y, b.z));
    }
#pragma unroll
    for (int o = 16; o > 0; o >>= 1) {
        s += __shfl_down_sync(0xffffffffu, s, o);
        m = fmaxf(m, __shfl_down_sync(0xffffffffu, m, o));
    }
    __shared__ float ss[8], sm[8];
    int lane = threadIdx.x & 31;
    int wid = threadIdx.x >> 5;
    if (lane == 0) { ss[wid] = s; sm[wid] = m; }
    __syncthreads();
    if (wid == 0) {
        int nw = blockDim.x >> 5;
        s = (lane < nw) ? ss[lane] : 0.0f;
        m = (lane < nw) ? sm[lane] : 0.0f;
#pragma unroll
        for (int o = 4; o > 0; o >>= 1) {
            s += __shfl_down_sync(0xffffffffu, s, o);
            m = fmaxf(m, __shfl_down_sync(0xffffffffu, m, o));
        }
        if (lane == 0) {
            atomicAdd(&out[0], s);
            atomicMax(reinterpret_cast<int*>(&out[1]), __float_as_int(m));
        }
    }
}

extern "C" void kernel_launch(void* const* d_in, const int* in_sizes, int n_in,
                              void* d_out, int out_size) {
    const float* pos = (const float*)d_in[0];
    const float* nsx = (const float*)d_in[1];
    const float* nsy = (const float*)d_in[2];
    const float* nsz = (const float*)d_in[3];
    float* out = (float*)d_out;

    // 1) zero (plain launch)
    k_zero<<<512, 256>>>(out);

    // 2) scatter — PDL-dependent on zero
    {
        cudaLaunchConfig_t cfg = {};
        cfg.gridDim = dim3((N_ + 255) / 256);
        cfg.blockDim = dim3(256);
        cudaLaunchAttribute attr[1];
        attr[0].id = cudaLaunchAttributeProgrammaticStreamSerialization;
        attr[0].val.programmaticStreamSerializationAllowed = 1;
        cfg.attrs = attr;
        cfg.numAttrs = 1;
        cudaLaunchKernelEx(&cfg, k_scatter, pos, nsx, nsy, nsz);
    }

    // 3) reduce — PDL-dependent on scatter
    {
        cudaLaunchConfig_t cfg = {};
        cfg.gridDim = dim3((NX_ * NY_) / 256);
        cfg.blockDim = dim3(256);
        cudaLaunchAttribute attr[1];
        attr[0].id = cudaLaunchAttributeProgrammaticStreamSerialization;
        attr[0].val.programmaticStreamSerializationAllowed = 1;
        cfg.attrs = attr;
        cfg.numAttrs = 1;
        cudaLaunchKernelEx(&cfg, k_reduce, out);
    }
}